// round 1
// baseline (speedup 1.0000x reference)
#include <cuda_runtime.h>
#include <cuda_bf16.h>

// Performer (FAVOR+) causal attention, chunked linear-attention decomposition.
// B=8, N=4096, D=256, M=256, DV=256. Chunk C=128, NC=32.
//
// out[t] = (phi_q[t] . S_t) / max(phi_q[t] . z_t, 1e-6)
//   S_t = sum_{i<=t} phi_k[i] (x) v[i],  z_t = sum_{i<=t} phi_k[i]
// phi(x)[m] = exp(proj[m] - rowmax(proj)) / sqrt(M)   (the -0.5||x||^2 term
// cancels against the rowmax shift), proj = x @ omega^T.
//
// Chunked: out = (tril(Pq Pk^T) V + Pq S_pre) / (rowsum(tril(Pq Pk^T)) + Pq z_pre)

#define BATCH 8
#define SEQ   4096
#define DD    256
#define MM    256
#define DVV   256
#define CHUNK 128
#define NCHUNK (SEQ / CHUNK)   // 32
#define KT    16

// Scratch (device globals; no allocation allowed)
__device__ float g_phiQ[BATCH * SEQ * MM];                 // 33.5 MB
__device__ float g_phiK[BATCH * SEQ * MM];                 // 33.5 MB
__device__ float g_S[BATCH * NCHUNK * MM * DVV];           // 67 MB (chunk states -> exclusive prefix)
__device__ float g_z[BATCH * NCHUNK * MM];                 // 256 KB

// ---------------------------------------------------------------------------
// Kernel 1: phi = exp(X @ omega^T - rowmax) / 16  for X in {Q, K_in}.
// Tile: 64 rows x 256 cols per CTA, blockDim (32,8), 8x8 micro per thread.
// rows: e*8+ty (e 0..7), cols: f*32+tx (f 0..7)  -> warp (fixed ty) owns 8 rows
// fully => rowmax via warp shuffle.
// ---------------------------------------------------------------------------
__global__ void __launch_bounds__(256) phi_kernel(const float* __restrict__ Q,
                                                  const float* __restrict__ Kin,
                                                  const float* __restrict__ W)
{
    __shared__ float Xs[KT][65];    // transposed: Xs[k][row]
    __shared__ float Ws[KT][257];   // transposed: Ws[k][m]

    const float* X  = (blockIdx.y == 0) ? Q : Kin;
    float*      Phi = (blockIdx.y == 0) ? g_phiQ : g_phiK;

    const int row0 = blockIdx.x * 64;
    const int tx = threadIdx.x, ty = threadIdx.y;
    const int tid = ty * 32 + tx;

    float acc[8][8];
#pragma unroll
    for (int e = 0; e < 8; e++)
#pragma unroll
        for (int f = 0; f < 8; f++) acc[e][f] = 0.f;

    for (int d0 = 0; d0 < DD; d0 += KT) {
        // Xs: 64 rows x 16 d, store transposed
#pragma unroll
        for (int e = 0; e < 4; e++) {
            int li = tid + e * 256;            // 0..1023
            int r = li >> 4, c = li & 15;
            Xs[c][r] = X[(size_t)(row0 + r) * DD + d0 + c];
        }
        // Ws: 256 m x 16 d, store transposed
#pragma unroll
        for (int e = 0; e < 16; e++) {
            int li = tid + e * 256;            // 0..4095
            int r = li >> 4, c = li & 15;
            Ws[c][r] = W[(size_t)r * DD + d0 + c];
        }
        __syncthreads();
#pragma unroll
        for (int k = 0; k < KT; k++) {
            float a[8], bb[8];
#pragma unroll
            for (int e = 0; e < 8; e++) a[e] = Xs[k][e * 8 + ty];
#pragma unroll
            for (int f = 0; f < 8; f++) bb[f] = Ws[k][f * 32 + tx];
#pragma unroll
            for (int e = 0; e < 8; e++)
#pragma unroll
                for (int f = 0; f < 8; f++) acc[e][f] = fmaf(a[e], bb[f], acc[e][f]);
        }
        __syncthreads();
    }

    // epilogue: per-row max over all 256 cols (8 local + warp shuffle), exp, /16
#pragma unroll
    for (int e = 0; e < 8; e++) {
        float mx = acc[e][0];
#pragma unroll
        for (int f = 1; f < 8; f++) mx = fmaxf(mx, acc[e][f]);
#pragma unroll
        for (int o = 16; o > 0; o >>= 1) mx = fmaxf(mx, __shfl_xor_sync(0xffffffffu, mx, o));
        const size_t rowoff = (size_t)(row0 + e * 8 + ty) * MM;
#pragma unroll
        for (int f = 0; f < 8; f++)
            Phi[rowoff + f * 32 + tx] = __expf(acc[e][f] - mx) * 0.0625f;
    }
}

// ---------------------------------------------------------------------------
// Kernel 2: chunk state contributions  S_c[m][dv] = sum_k phiK[k][m] * V[k][dv]
// grid (2 dv-tiles, 2 m-tiles, B*NC). 128x128 tile, blockDim (32,8),
// micro 16 rows (e*8+ty) x 4 cols (f*32+tx).
// ---------------------------------------------------------------------------
__global__ void __launch_bounds__(256) scontrib_kernel(const float* __restrict__ V)
{
    __shared__ float As[KT][128];   // phiK slice [k][m]
    __shared__ float Bs[KT][128];   // V slice    [k][dv]

    const int bc = blockIdx.z;
    const int b = bc / NCHUNK, c = bc % NCHUNK;
    const int m0  = blockIdx.y * 128;
    const int dv0 = blockIdx.x * 128;
    const size_t base = (size_t)b * SEQ + (size_t)c * CHUNK;
    const float* phiK = g_phiK + base * MM;
    const float* Vb   = V + base * DVV;
    float* Sout = g_S + (size_t)bc * MM * DVV;

    const int tx = threadIdx.x, ty = threadIdx.y;
    const int tid = ty * 32 + tx;

    float acc[16][4];
#pragma unroll
    for (int e = 0; e < 16; e++)
#pragma unroll
        for (int f = 0; f < 4; f++) acc[e][f] = 0.f;

    for (int k0 = 0; k0 < CHUNK; k0 += KT) {
#pragma unroll
        for (int e = 0; e < 8; e++) {
            int li = tid + e * 256;           // 2048 = 16*128
            int r = li >> 7, cc = li & 127;
            As[r][cc] = phiK[(size_t)(k0 + r) * MM + m0 + cc];
            Bs[r][cc] = Vb[(size_t)(k0 + r) * DVV + dv0 + cc];
        }
        __syncthreads();
#pragma unroll
        for (int k = 0; k < KT; k++) {
            float a[16], bb[4];
#pragma unroll
            for (int e = 0; e < 16; e++) a[e] = As[k][e * 8 + ty];
#pragma unroll
            for (int f = 0; f < 4; f++) bb[f] = Bs[k][f * 32 + tx];
#pragma unroll
            for (int e = 0; e < 16; e++)
#pragma unroll
                for (int f = 0; f < 4; f++) acc[e][f] = fmaf(a[e], bb[f], acc[e][f]);
        }
        __syncthreads();
    }
#pragma unroll
    for (int e = 0; e < 16; e++) {
        const size_t rowoff = (size_t)(m0 + e * 8 + ty) * DVV + dv0;
#pragma unroll
        for (int f = 0; f < 4; f++) Sout[rowoff + f * 32 + tx] = acc[e][f];
    }
}

// Kernel 2b: per-chunk column sums of phiK -> g_z[b][c][m]
__global__ void __launch_bounds__(256) zsum_kernel()
{
    const int bc = blockIdx.x;
    const int m = threadIdx.x;
    const size_t base = ((size_t)(bc / NCHUNK) * SEQ + (size_t)(bc % NCHUNK) * CHUNK) * MM;
    float s = 0.f;
#pragma unroll 8
    for (int k = 0; k < CHUNK; k++) s += g_phiK[base + (size_t)k * MM + m];
    g_z[(size_t)bc * MM + m] = s;
}

// Kernel 3a: in-place exclusive prefix over chunks for S (per b,m,dv lane)
__global__ void __launch_bounds__(256) prefixS_kernel()
{
    const size_t g = (size_t)blockIdx.x * 256 + threadIdx.x;   // B*M*DV lanes
    const size_t b = g / (MM * DVV);
    const size_t r = g % (MM * DVV);
    float* p = g_S + b * (size_t)NCHUNK * MM * DVV + r;
    float run = 0.f;
#pragma unroll 4
    for (int c = 0; c < NCHUNK; c++) {
        const size_t off = (size_t)c * MM * DVV;
        float v = p[off];
        p[off] = run;
        run += v;
    }
}

// Kernel 3b: in-place exclusive prefix over chunks for z
__global__ void __launch_bounds__(256) prefixz_kernel()
{
    const int g = blockIdx.x * 256 + threadIdx.x;   // B*M lanes
    const int b = g / MM, m = g % MM;
    float* p = g_z + (size_t)b * NCHUNK * MM + m;
    float run = 0.f;
#pragma unroll
    for (int c = 0; c < NCHUNK; c++) {
        float v = p[c * MM];
        p[c * MM] = run;
        run += v;
    }
}

// ---------------------------------------------------------------------------
// Kernel 4: per (b, chunk):
//   A = tril(Pq Pk^T)  (128x128, K=256), kept in smem
//   num = A @ V_chunk + Pq @ S_pre      (128x256)
//   den = rowsum(A) + Pq . z_pre        (128)
//   out = num / max(den, 1e-6)
// blockDim (32,8); 128-wide tiles, micro 16x4.
// ---------------------------------------------------------------------------
__global__ void __launch_bounds__(256) chunk_kernel(const float* __restrict__ V,
                                                    float* __restrict__ Out)
{
    extern __shared__ float sm[];
    float* As    = sm;                      // 128*128 = 16384
    float* Qt    = As + 128 * 128;          // KT*129  = 2064 (transposed phiQ tile)
    float* Kt    = Qt + KT * 129;           // KT*129  = 2064 (transposed phiK tile)
    float* Bs    = Kt + KT * 129;           // KT*128  = 2048 (V / S_pre tile)
    float* zs    = Bs + KT * 128;           // 256
    float* dsum  = zs + 256;                // 128 (den_intra)
    float* dpart = dsum + 128;              // 256 (den_inter partials)
    float* rden  = dpart + 256;             // 128 (1/den)

    const int bc = blockIdx.x;
    const int b = bc / NCHUNK, c = bc % NCHUNK;
    const size_t base = (size_t)b * SEQ + (size_t)c * CHUNK;
    const float* phiQ = g_phiQ + base * MM;
    const float* phiK = g_phiK + base * MM;
    const float* Vb   = V + base * DVV;
    const float* Spre = g_S + (size_t)bc * MM * DVV;
    const float* zpre = g_z + (size_t)bc * MM;

    const int tx = threadIdx.x, ty = threadIdx.y;
    const int tid = ty * 32 + tx;

    // ---------------- Phase A: A = Pq Pk^T over K=256 (m) ----------------
    float acc[16][4];
#pragma unroll
    for (int e = 0; e < 16; e++)
#pragma unroll
        for (int f = 0; f < 4; f++) acc[e][f] = 0.f;

    for (int m0 = 0; m0 < MM; m0 += KT) {
#pragma unroll
        for (int e = 0; e < 8; e++) {
            int li = tid + e * 256;            // 2048 = 128*16
            int r = li >> 4, cc = li & 15;
            Qt[cc * 129 + r] = phiQ[(size_t)r * MM + m0 + cc];
            Kt[cc * 129 + r] = phiK[(size_t)r * MM + m0 + cc];
        }
        __syncthreads();
#pragma unroll
        for (int k = 0; k < KT; k++) {
            float a[16], bb[4];
#pragma unroll
            for (int e = 0; e < 16; e++) a[e] = Qt[k * 129 + e * 8 + ty];
#pragma unroll
            for (int f = 0; f < 4; f++) bb[f] = Kt[k * 129 + f * 32 + tx];
#pragma unroll
            for (int e = 0; e < 16; e++)
#pragma unroll
                for (int f = 0; f < 4; f++) acc[e][f] = fmaf(a[e], bb[f], acc[e][f]);
        }
        __syncthreads();
    }

    // mask + write A to smem + den_intra (rowsum of tril)
#pragma unroll
    for (int e = 0; e < 16; e++) {
        const int row = e * 8 + ty;
        float dp = 0.f;
#pragma unroll
        for (int f = 0; f < 4; f++) {
            const int col = f * 32 + tx;
            const float v = (col <= row) ? acc[e][f] : 0.f;
            As[row * 128 + col] = v;
            dp += v;
        }
#pragma unroll
        for (int o = 16; o > 0; o >>= 1) dp += __shfl_xor_sync(0xffffffffu, dp, o);
        if (tx == 0) dsum[row] = dp;
    }
    zs[tid] = zpre[tid];
    __syncthreads();

    // den_inter: 2 threads per row, each half of the 256 m's
    {
        const int row = tid >> 1;
        const int half = tid & 1;
        const float* q = phiQ + (size_t)row * MM + half * 128;
        const float* z = zs + half * 128;
        float p = 0.f;
#pragma unroll 8
        for (int m = 0; m < 128; m++) p = fmaf(q[m], z[m], p);
        dpart[tid] = p;
    }
    __syncthreads();
    if (tid < 128) {
        const float d = dsum[tid] + dpart[2 * tid] + dpart[2 * tid + 1];
        rden[tid] = 1.f / fmaxf(d, 1e-6f);
    }
    __syncthreads();

    // ---------------- Phase B: num = A@V + Pq@Spre, two 128-wide dv halves
    for (int dvh = 0; dvh < 2; dvh++) {
        const int dv0 = dvh * 128;
        float acc2[16][4];
#pragma unroll
        for (int e = 0; e < 16; e++)
#pragma unroll
            for (int f = 0; f < 4; f++) acc2[e][f] = 0.f;

        // intra: K = 128 (j), A from smem (broadcast reads), V tiles in Bs
        for (int j0 = 0; j0 < CHUNK; j0 += KT) {
#pragma unroll
            for (int e = 0; e < 8; e++) {
                int li = tid + e * 256;        // 2048 = 16*128
                int r = li >> 7, cc = li & 127;
                Bs[r * 128 + cc] = Vb[(size_t)(j0 + r) * DVV + dv0 + cc];
            }
            __syncthreads();
#pragma unroll
            for (int k = 0; k < KT; k++) {
                float a[16], bb[4];
#pragma unroll
                for (int e = 0; e < 16; e++) a[e] = As[(e * 8 + ty) * 128 + j0 + k];
#pragma unroll
                for (int f = 0; f < 4; f++) bb[f] = Bs[k * 128 + f * 32 + tx];
#pragma unroll
                for (int e = 0; e < 16; e++)
#pragma unroll
                    for (int f = 0; f < 4; f++) acc2[e][f] = fmaf(a[e], bb[f], acc2[e][f]);
            }
            __syncthreads();
        }

        // inter: K = 256 (m), Pq transposed tiles in Qt, S_pre tiles in Bs
        for (int m0 = 0; m0 < MM; m0 += KT) {
#pragma unroll
            for (int e = 0; e < 8; e++) {
                int li = tid + e * 256;
                {   // Qt: 128 rows x 16 m, transposed
                    int r = li >> 4, cc = li & 15;
                    Qt[cc * 129 + r] = phiQ[(size_t)r * MM + m0 + cc];
                }
                {   // Bs: 16 m-rows x 128 dv
                    int r = li >> 7, cc = li & 127;
                    Bs[r * 128 + cc] = Spre[(size_t)(m0 + r) * DVV + dv0 + cc];
                }
            }
            __syncthreads();
#pragma unroll
            for (int k = 0; k < KT; k++) {
                float a[16], bb[4];
#pragma unroll
                for (int e = 0; e < 16; e++) a[e] = Qt[k * 129 + e * 8 + ty];
#pragma unroll
                for (int f = 0; f < 4; f++) bb[f] = Bs[k * 128 + f * 32 + tx];
#pragma unroll
                for (int e = 0; e < 16; e++)
#pragma unroll
                    for (int f = 0; f < 4; f++) acc2[e][f] = fmaf(a[e], bb[f], acc2[e][f]);
            }
            __syncthreads();
        }

        // epilogue
#pragma unroll
        for (int e = 0; e < 16; e++) {
            const int row = e * 8 + ty;
            const float r = rden[row];
            const size_t rowoff = (base + row) * DVV + dv0;
#pragma unroll
            for (int f = 0; f < 4; f++)
                Out[rowoff + f * 32 + tx] = acc2[e][f] * r;
        }
    }
}

// ---------------------------------------------------------------------------
extern "C" void kernel_launch(void* const* d_in, const int* in_sizes, int n_in,
                              void* d_out, int out_size)
{
    (void)in_sizes; (void)n_in; (void)out_size;
    const float* Q   = (const float*)d_in[0];
    const float* Kin = (const float*)d_in[1];
    const float* V   = (const float*)d_in[2];
    const float* W   = (const float*)d_in[3];
    // d_in[4] is the causal flag; this dataset is always causal=1.
    float* Out = (float*)d_out;

    dim3 blk(32, 8);

    // 1) phi for Q and K
    phi_kernel<<<dim3(BATCH * SEQ / 64, 2), blk>>>(Q, Kin, W);

    // 2) chunk state contributions + chunk z sums
    scontrib_kernel<<<dim3(2, 2, BATCH * NCHUNK), blk>>>(V);
    zsum_kernel<<<BATCH * NCHUNK, 256>>>();

    // 3) exclusive prefixes across chunks
    prefixS_kernel<<<(BATCH * MM * DVV) / 256, 256>>>();
    prefixz_kernel<<<(BATCH * MM) / 256, 256>>>();

    // 4) main per-chunk kernel
    const int smem_bytes = (128 * 128 + 2 * KT * 129 + KT * 128 + 256 + 128 + 256 + 128) * 4;
    cudaFuncSetAttribute(chunk_kernel, cudaFuncAttributeMaxDynamicSharedMemorySize, smem_bytes);
    chunk_kernel<<<BATCH * NCHUNK, blk, smem_bytes>>>(V, Out);
}